// round 8
// baseline (speedup 1.0000x reference)
#include <cuda_runtime.h>
#include <cstdint>

#define NN 8192
#define NB 256                 // buckets == chunks
#define NCHUNK 256
#define TPREP 1024
#define EPT (NN / TPREP)       // 8 elements per thread

// Scratch (device globals — no allocation allowed in kernel_launch).
// Every array fully rewritten each launch -> graph-replay deterministic.
__device__ float g_s[NN];        // s[j] by original index
__device__ float g_ss[NN];       // s in bucket-sorted order
__device__ float g_ws[NN];       // wmax in bucket-sorted order
__device__ int   g_idx[NN];      // original index in bucket-sorted order
__device__ float g_cmin[NCHUNK]; // suffix min of s over chunks >= c
__device__ float g_cwub[NCHUNK]; // suffix max of wmax over chunks >= c
__device__ float g_cnsw[NCHUNK]; // suffix max of (-s*w) over chunks >= c

// ---------------------------------------------------------------------------
// Kernel 1: ONE CTA, 1024 threads, zero atomics.
// s/wmax -> 256-bucket counting sort (per-warp histograms + match_any ranks)
// -> hierarchical scan -> scatter -> chunk suffix bounds.
// ---------------------------------------------------------------------------
__global__ __launch_bounds__(TPREP)
void prep_kernel(const float* __restrict__ x, const float* __restrict__ Wphi) {
    __shared__ int   counts[32 * NB];   // [warp][bucket], 32 KB
    __shared__ int   warpsums[32];
    __shared__ float cmn[NCHUNK], cwx[NCHUNK], cns[NCHUNK];

    const int t    = threadIdx.x;
    const int lane = t & 31;
    const int wid  = t >> 5;

    // Zero per-warp histograms
    #pragma unroll
    for (int q = 0; q < EPT; q++) counts[t + q * TPREP] = 0;
    __syncthreads();

    // Phase 1: s, wmax, bucket, per-warp rank (coalesced j = q*1024 + t)
    float sv[EPT], wv[EPT];
    int   bv[EPT], rk[EPT];
    #pragma unroll
    for (int q = 0; q < EPT; q++) {
        int j = q * TPREP + t;
        float s = x[3 * j + 0] + x[3 * j + 1] + x[3 * j + 2];
        float w0 = Wphi[j], w1 = Wphi[NN + j], w2 = Wphi[2 * NN + j];
        float w = fmaxf(w0, fmaxf(w1, w2));
        g_s[j] = s;
        int b = (int)(s * (NB / 3.0f));
        b = max(0, min(NB - 1, b));

        unsigned mask = __match_any_sync(0xffffffffu, b);
        int leader = __ffs(mask) - 1;
        int cbase = counts[wid * NB + b];          // same addr per group -> broadcast
        __syncwarp();
        if (lane == leader) counts[wid * NB + b] = cbase + __popc(mask);
        __syncwarp();
        rk[q] = cbase + __popc(mask & ((1u << lane) - 1u));
        sv[q] = s; wv[q] = w; bv[q] = b;
    }
    __syncthreads();

    // Phase 2: exclusive scan of the 8192 counters in order idx = b*32 + w
    int vals[EPT];
    int lsum = 0;
    #pragma unroll
    for (int q = 0; q < EPT; q++) {
        int idx = t * EPT + q;
        vals[q] = counts[(idx & 31) * NB + (idx >> 5)];
        lsum += vals[q];
    }
    int inc = lsum;
    #pragma unroll
    for (int off = 1; off < 32; off <<= 1) {
        int n = __shfl_up_sync(0xffffffffu, inc, off);
        if (lane >= off) inc += n;
    }
    if (lane == 31) warpsums[wid] = inc;
    __syncthreads();
    if (wid == 0) {
        int ws = warpsums[lane];
        int winc = ws;
        #pragma unroll
        for (int off = 1; off < 32; off <<= 1) {
            int n = __shfl_up_sync(0xffffffffu, winc, off);
            if (lane >= off) winc += n;
        }
        warpsums[lane] = winc - ws;    // exclusive warp offset
    }
    __syncthreads();
    {
        int run = warpsums[wid] + (inc - lsum);    // global exclusive base
        #pragma unroll
        for (int q = 0; q < EPT; q++) {
            int idx = t * EPT + q;
            counts[(idx & 31) * NB + (idx >> 5)] = run;   // each entry owned by one thread
            run += vals[q];
        }
    }
    __syncthreads();

    // Phase 3: scatter (position = counter base + recorded rank)
    #pragma unroll
    for (int q = 0; q < EPT; q++) {
        int j = q * TPREP + t;
        int pos = counts[wid * NB + bv[q]] + rk[q];
        g_ss[pos]  = sv[q];
        g_ws[pos]  = wv[q];
        g_idx[pos] = j;
    }
    __syncthreads();   // block-scope: global writes above visible to the block

    // Phase 4: per-chunk stats (chunk c = sorted positions [32c, 32c+32))
    if (t < NCHUNK) {
        float mn = 3.0e38f, mx = -3.0e38f, ns = -3.0e38f;
        #pragma unroll 8
        for (int q = 0; q < 32; q++) {
            float s = g_ss[t * 32 + q];
            float w = g_ws[t * 32 + q];
            mn = fminf(mn, s);
            mx = fmaxf(mx, w);
            ns = fmaxf(ns, -s * w);
        }
        cmn[t] = mn; cwx[t] = mx; cns[t] = ns;
    }
    __syncthreads();

    // Phase 5: suffix scan over 256 chunks — single warp, 8 chunks/lane
    if (t < 32) {
        float lm[8], lw[8], ln[8];
        float amn = 3.0e38f, amx = -3.0e38f, ans = -3.0e38f;
        #pragma unroll
        for (int q = 0; q < 8; q++) {
            lm[q] = cmn[t * 8 + q];
            lw[q] = cwx[t * 8 + q];
            ln[q] = cns[t * 8 + q];
            amn = fminf(amn, lm[q]);
            amx = fmaxf(amx, lw[q]);
            ans = fmaxf(ans, ln[q]);
        }
        float smn = amn, smx = amx, sns = ans;
        #pragma unroll
        for (int off = 1; off < 32; off <<= 1) {
            float a = __shfl_down_sync(0xffffffffu, smn, off);
            float b = __shfl_down_sync(0xffffffffu, smx, off);
            float c = __shfl_down_sync(0xffffffffu, sns, off);
            if (lane + off < 32) {
                smn = fminf(smn, a); smx = fmaxf(smx, b); sns = fmaxf(sns, c);
            }
        }
        float tmn = __shfl_down_sync(0xffffffffu, smn, 1);
        float tmx = __shfl_down_sync(0xffffffffu, smx, 1);
        float tns = __shfl_down_sync(0xffffffffu, sns, 1);
        if (lane == 31) { tmn = 3.0e38f; tmx = -3.0e38f; tns = -3.0e38f; }
        float rmn = tmn, rmx = tmx, rns = tns;
        #pragma unroll
        for (int q = 7; q >= 0; q--) {
            rmn = fminf(rmn, lm[q]);
            rmx = fmaxf(rmx, lw[q]);
            rns = fmaxf(rns, ln[q]);
            g_cmin[t * 8 + q] = rmn;
            g_cwub[t * 8 + q] = rmx;
            g_cnsw[t * 8 + q] = rns;
        }
    }
}

// ---------------------------------------------------------------------------
// Kernel 2: warp per row — 32 candidates/iter, prefetch next chunk, dual bound
// ---------------------------------------------------------------------------
__global__ __launch_bounds__(256)
void probe_kernel(const int* __restrict__ adj, float* __restrict__ out) {
    const int lane = threadIdx.x & 31;
    const int warp = threadIdx.x >> 5;
    const int i = blockIdx.x * 8 + warp;

    const float si = g_s[i];
    const int* __restrict__ arow = adj + (size_t)i * NN;

    float best = 0.0f;   // reference max always includes T[i,i] = 0

    int a = __ldg(&arow[g_idx[lane]]);

    for (int c = 0; c < NCHUNK; c++) {
        // Prefetch next chunk's adjacency before the reduce (hides DRAM latency)
        int na = 0;
        if (c + 1 < NCHUNK)
            na = __ldg(&arow[g_idx[(c + 1) * 32 + lane]]);

        const int k = c * 32 + lane;
        float d = si - g_ss[k];
        float contrib = (d > 0.0f && a) ? d * g_ws[k] : 0.0f;

        #pragma unroll
        for (int off = 16; off; off >>= 1)
            contrib = fmaxf(contrib, __shfl_xor_sync(0xffffffffu, contrib, off));
        best = fmaxf(best, contrib);

        if (c + 1 < NCHUNK) {
            // Two safe upper bounds on everything in chunks >= c+1:
            //  b1: (si - min s) * max w        (fp-monotone, exact-safe)
            //  b2: si*max(w) + max(-s*w) + slack (slack >> total rounding error)
            float b1 = (si - g_cmin[c + 1]) * g_cwub[c + 1];
            float b2 = si * g_cwub[c + 1] + g_cnsw[c + 1] + 1e-5f;
            if (fminf(b1, b2) <= best) break;
            a = na;
        }
    }

    if (lane == 0) {
        out[i * 3 + 0] = best;
        out[i * 3 + 1] = best;
        out[i * 3 + 2] = best;
    }
}

extern "C" void kernel_launch(void* const* d_in, const int* in_sizes, int n_in,
                              void* d_out, int out_size) {
    const float* x    = (const float*)d_in[0];
    const int*   adj  = (const int*)d_in[1];
    const float* Wphi = (const float*)d_in[2];
    // d_in[3] (W_theta) is unused in the forward pass.
    float* out = (float*)d_out;

    prep_kernel<<<1, TPREP>>>(x, Wphi);
    probe_kernel<<<NN / 8, 256>>>(adj, out);
}

// round 9
// speedup vs baseline: 2.2461x; 2.2461x over previous
#include <cuda_runtime.h>
#include <cstdint>

#define NN 8192
#define KB 4096               // histogram buckets (fine sort -> tight bounds)
#define NCHUNK 256            // 256 chunks of 32 sorted candidates

// Scratch (device globals — no allocation allowed in kernel_launch).
// Zero-initialized at load; every array is re-established each launch chain.
__device__ float    g_s[NN];          // s[j] by original index
__device__ float    g_wm[NN];         // wmax[j] by original index
__device__ int      g_bk[NN];         // bucket id by original index
__device__ __align__(16) int g_hist[KB];  // histogram (left ZEROED by scan for next run)
__device__ __align__(16) int g_cur[KB];   // exclusive offsets -> scatter cursors
__device__ float    g_ss[NN];         // s in bucket-sorted order
__device__ float    g_ws[NN];         // wmax in bucket-sorted order
__device__ int      g_idx[NN];        // original index in bucket-sorted order
__device__ unsigned g_csmin[NCHUNK];  // per-chunk min s   (positive-float bits, atomicMin)
__device__ unsigned g_cwmax[NCHUNK];  // per-chunk max w   (positive-float bits, atomicMax)
__device__ unsigned g_cnsmin[NCHUNK]; // per-chunk max -s*w (negative-float bits, atomicMin)

// K1: per-element s, wmax, bucket; histogram via spread global atomics
__global__ __launch_bounds__(128)
void bucket_kernel(const float* __restrict__ x, const float* __restrict__ Wphi) {
    int j = blockIdx.x * 128 + threadIdx.x;
    float s = x[3 * j + 0] + x[3 * j + 1] + x[3 * j + 2];
    float w0 = Wphi[j], w1 = Wphi[NN + j], w2 = Wphi[2 * NN + j];
    float w = fmaxf(w0, fmaxf(w1, w2));
    int b = (int)(s * (KB / 3.0f));
    b = max(0, min(KB - 1, b));
    g_s[j]  = s;
    g_wm[j] = w;
    g_bk[j] = b;
    atomicAdd(&g_hist[b], 1);
}

// K2: exclusive scan hist -> cur; zero hist for the next replay; init chunk stats
__global__ __launch_bounds__(1024)
void scan_kernel() {
    __shared__ int warpsums[32];
    const int t = threadIdx.x, lane = t & 31, wid = t >> 5;

    int4 h = reinterpret_cast<const int4*>(g_hist)[t];      // buckets 4t..4t+3
    reinterpret_cast<int4*>(g_hist)[t] = make_int4(0, 0, 0, 0);  // ready for next run

    int lsum = h.x + h.y + h.z + h.w;
    int inc = lsum;
    #pragma unroll
    for (int off = 1; off < 32; off <<= 1) {
        int n = __shfl_up_sync(0xffffffffu, inc, off);
        if (lane >= off) inc += n;
    }
    if (lane == 31) warpsums[wid] = inc;
    __syncthreads();
    if (wid == 0) {
        int ws = warpsums[lane];
        int winc = ws;
        #pragma unroll
        for (int off = 1; off < 32; off <<= 1) {
            int n = __shfl_up_sync(0xffffffffu, winc, off);
            if (lane >= off) winc += n;
        }
        warpsums[lane] = winc - ws;   // exclusive warp offset
    }
    __syncthreads();
    int base = warpsums[wid] + (inc - lsum);
    int4 o;
    o.x = base;
    o.y = base + h.x;
    o.z = base + h.x + h.y;
    o.w = base + h.x + h.y + h.z;
    reinterpret_cast<int4*>(g_cur)[t] = o;

    if (t < NCHUNK) {
        g_csmin[t]  = 0x7F800000u;   // +inf
        g_cwmax[t]  = 0u;            // 0.0f (all w > 0)
        g_cnsmin[t] = 0xFFFFFFFFu;   // most-negative float bits
    }
}

// K3: scatter into sorted arrays; fold per-chunk stats in via bitwise atomics.
// s>0 and w>0 -> int bits monotone; -s*w<=0 -> uint bits reverse-monotone.
__global__ __launch_bounds__(128)
void scatter_kernel() {
    int j = blockIdx.x * 128 + threadIdx.x;
    float s = g_s[j];
    float w = g_wm[j];
    int pos = atomicAdd(&g_cur[g_bk[j]], 1);
    g_ss[pos]  = s;
    g_ws[pos]  = w;
    g_idx[pos] = j;
    int c = pos >> 5;
    atomicMin(&g_csmin[c],  __float_as_uint(s));
    atomicMax(&g_cwmax[c],  __float_as_uint(w));
    atomicMin(&g_cnsmin[c], __float_as_uint(-s * w));   // uint-min == float-max (negatives)
}

// K4: warp per row — prologue computes suffix bounds in smem, then the
// 32-candidate/iter pruned scan with prefetch + dual safe bound.
__global__ __launch_bounds__(256)
void probe_kernel(const int* __restrict__ adj, float* __restrict__ out) {
    __shared__ float s_cmin[NCHUNK], s_cwub[NCHUNK], s_cnsw[NCHUNK];

    const int t = threadIdx.x;
    const int lane = t & 31;
    const int warp = t >> 5;

    // Load raw chunk stats (hot L2) into smem
    s_cmin[t] = __uint_as_float(g_csmin[t]);
    s_cwub[t] = __uint_as_float(g_cwmax[t]);
    s_cnsw[t] = __uint_as_float(g_cnsmin[t]);
    __syncthreads();

    // Warp 0: in-place suffix scan over 256 chunks (8 per lane)
    if (t < 32) {
        float lm[8], lw[8], ln[8];
        float amn = 3.0e38f, amx = -3.0e38f, ans = -3.0e38f;
        #pragma unroll
        for (int q = 0; q < 8; q++) {
            lm[q] = s_cmin[t * 8 + q];
            lw[q] = s_cwub[t * 8 + q];
            ln[q] = s_cnsw[t * 8 + q];
            amn = fminf(amn, lm[q]);
            amx = fmaxf(amx, lw[q]);
            ans = fmaxf(ans, ln[q]);
        }
        float smn = amn, smx = amx, sns = ans;
        #pragma unroll
        for (int off = 1; off < 32; off <<= 1) {
            float a = __shfl_down_sync(0xffffffffu, smn, off);
            float b = __shfl_down_sync(0xffffffffu, smx, off);
            float c = __shfl_down_sync(0xffffffffu, sns, off);
            if (lane + off < 32) {
                smn = fminf(smn, a); smx = fmaxf(smx, b); sns = fmaxf(sns, c);
            }
        }
        float tmn = __shfl_down_sync(0xffffffffu, smn, 1);
        float tmx = __shfl_down_sync(0xffffffffu, smx, 1);
        float tns = __shfl_down_sync(0xffffffffu, sns, 1);
        if (lane == 31) { tmn = 3.0e38f; tmx = -3.0e38f; tns = -3.0e38f; }
        float rmn = tmn, rmx = tmx, rns = tns;
        #pragma unroll
        for (int q = 7; q >= 0; q--) {
            rmn = fminf(rmn, lm[q]);
            rmx = fmaxf(rmx, lw[q]);
            rns = fmaxf(rns, ln[q]);
            s_cmin[t * 8 + q] = rmn;
            s_cwub[t * 8 + q] = rmx;
            s_cnsw[t * 8 + q] = rns;
        }
    }
    __syncthreads();

    const int i = blockIdx.x * 8 + warp;
    const float si = g_s[i];
    const int* __restrict__ arow = adj + (size_t)i * NN;

    float best = 0.0f;   // reference max always includes T[i,i] = 0

    int a = __ldg(&arow[g_idx[lane]]);

    for (int c = 0; c < NCHUNK; c++) {
        // Prefetch next chunk's adjacency before the reduce (hides DRAM latency)
        int na = 0;
        if (c + 1 < NCHUNK)
            na = __ldg(&arow[g_idx[(c + 1) * 32 + lane]]);

        const int k = c * 32 + lane;
        float d = si - g_ss[k];
        float contrib = (d > 0.0f && a) ? d * g_ws[k] : 0.0f;

        #pragma unroll
        for (int off = 16; off; off >>= 1)
            contrib = fmaxf(contrib, __shfl_xor_sync(0xffffffffu, contrib, off));
        best = fmaxf(best, contrib);

        if (c + 1 < NCHUNK) {
            // Two safe upper bounds on everything in chunks >= c+1:
            //  b1: (si - min s) * max w          (fp-monotone, exact-safe)
            //  b2: si*max(w) + max(-s*w) + slack (slack >> total rounding error)
            float b1 = (si - s_cmin[c + 1]) * s_cwub[c + 1];
            float b2 = si * s_cwub[c + 1] + s_cnsw[c + 1] + 1e-5f;
            if (fminf(b1, b2) <= best) break;
            a = na;
        }
    }

    if (lane == 0) {
        out[i * 3 + 0] = best;
        out[i * 3 + 1] = best;
        out[i * 3 + 2] = best;
    }
}

extern "C" void kernel_launch(void* const* d_in, const int* in_sizes, int n_in,
                              void* d_out, int out_size) {
    const float* x    = (const float*)d_in[0];
    const int*   adj  = (const int*)d_in[1];
    const float* Wphi = (const float*)d_in[2];
    // d_in[3] (W_theta) is unused in the forward pass.
    float* out = (float*)d_out;

    bucket_kernel<<<NN / 128, 128>>>(x, Wphi);
    scan_kernel<<<1, 1024>>>();
    scatter_kernel<<<NN / 128, 128>>>();
    probe_kernel<<<NN / 8, 256>>>(adj, out);
}